// round 5
// baseline (speedup 1.0000x reference)
#include <cuda_runtime.h>
#include <math.h>
#include <stdint.h>

#define D 128
#define NMAX 100000
#define SECT 256

#define PI_F      3.14159265358979f
#define HALFPI_F  1.57079632679490f
#define TWOPI_F   6.28318530717959f

// ---------------- scratch (static device globals; no runtime alloc) ------------
__device__ float g_acc[(size_t)NMAX * D];   // 51.2 MB scatter accumulator
__device__ float g_cnt[NMAX];               // per-dst edge counts (float, exact ints)
__device__ float g_bounds[SECT];            // sorted sector boundary angles
__device__ float g_U[SECT * D];             // sector tables: pe = w0*U[s] + w1*V[s]
__device__ float g_V[SECT * D];
__device__ float g_colsum[D];               // BN stats
__device__ float g_colsq[D];
__device__ int   g_ei64;                    // 1 if edge_index is int64, 0 if int32

// ---------------- K-1: detect edge_index dtype ---------------------------------
// int64 little-endian with values in [0, N): every odd 32-bit word is 0.
// int32 random indices: P(32 probed odd words all zero) ~ 1e-160. Deterministic.
__global__ void k_detect(const int* __restrict__ w) {
    if (threadIdx.x == 0 && blockIdx.x == 0) {
        int all0 = 1;
        #pragma unroll
        for (int j = 1; j < 64; j += 2) all0 &= (w[j] == 0);
        g_ei64 = all0;
    }
}

// ---------------- K0: zero scratch ---------------------------------------------
__global__ void k_zero(int n) {
    int nd4 = n * (D / 4);
    float4 z = make_float4(0.f, 0.f, 0.f, 0.f);
    int stride = gridDim.x * blockDim.x;
    for (int i = blockIdx.x * blockDim.x + threadIdx.x; i < nd4; i += stride)
        reinterpret_cast<float4*>(g_acc)[i] = z;
    for (int i = blockIdx.x * blockDim.x + threadIdx.x; i < n; i += stride)
        g_cnt[i] = 0.f;
    if (blockIdx.x == 0 && threadIdx.x < D) {
        g_colsum[threadIdx.x] = 0.f;
        g_colsq[threadIdx.x]  = 0.f;
    }
}

// ---------------- K1: sector boundary angles (1 block, 256 threads) ------------
// relu mask for dim d flips where A_d*cos(th) + B_d*sin(th) = 0, i.e. at
// phi_d +/- pi/2 with phi_d = atan2(B_d, A_d). 256 boundaries -> rank-sort.
__global__ void k_bounds(const float* __restrict__ pw1) {
    __shared__ float raw[SECT];
    int t = threadIdx.x;
    if (t < D) {
        float A = pw1[t];          // pos_w1[0, t]
        float B = pw1[D + t];      // pos_w1[1, t]
        float phi = atan2f(B, A);
        float c0 = phi + HALFPI_F; if (c0 >  PI_F) c0 -= TWOPI_F;
        float c1 = phi - HALFPI_F; if (c1 < -PI_F) c1 += TWOPI_F;
        raw[2 * t]     = c0;
        raw[2 * t + 1] = c1;
    }
    __syncthreads();
    float v = raw[t];
    int rank = 0;
    #pragma unroll 8
    for (int j = 0; j < SECT; j++) {
        float u = raw[j];
        rank += (u < v) || (u == v && j < t);
    }
    g_bounds[rank] = v;
}

// ---------------- K2: sector tables U,V (256 blocks x 128 threads) -------------
__global__ void k_sectors(const float* __restrict__ pw1, const float* __restrict__ pw2) {
    __shared__ float Am[D], Bm[D];
    __shared__ float thc_s;
    int s = blockIdx.x;
    int k = threadIdx.x;
    if (k == 0) {
        float b0 = g_bounds[s];
        float b1 = (s < SECT - 1) ? g_bounds[s + 1] : (g_bounds[0] + TWOPI_F);
        thc_s = 0.5f * (b0 + b1);   // sector-center angle (may exceed pi; sin/cos ok)
    }
    __syncthreads();
    float c = cosf(thc_s), sn = sinf(thc_s);
    float A = pw1[k], B = pw1[D + k];
    bool m = fmaf(A, c, B * sn) > 0.f;
    Am[k] = m ? A : 0.f;
    Bm[k] = m ? B : 0.f;
    __syncthreads();
    float u = 0.f, v = 0.f;
    #pragma unroll 8
    for (int d = 0; d < D; d++) {
        float w = pw2[d * D + k];          // coalesced across k
        u = fmaf(Am[d], w, u);
        v = fmaf(Bm[d], w, v);
    }
    g_U[s * D + k] = u;
    g_V[s * D + k] = v;
}

// ---------------- K3: edge gather + message + scatter (1 warp / edge) ----------
__global__ __launch_bounds__(256) void k_edges(const float* __restrict__ x,
                                               const void* __restrict__ ei_raw,
                                               const float* __restrict__ ew, int E) {
    __shared__ float sb[SECT];
    int t = threadIdx.x;
    sb[t] = g_bounds[t];               // blockDim == 256
    __syncthreads();
    const long long* ei64 = (const long long*)ei_raw;
    const int*       ei32 = (const int*)ei_raw;
    int is64 = g_ei64;
    int lane = t & 31;
    int gw = blockIdx.x * 8 + (t >> 5);
    int nwarps = gridDim.x * 8;
    for (int e = gw; e < E; e += nwarps) {
        int src = 0, dst = 0, sct = 0;
        float w0 = 0.f, w1 = 0.f;
        if (lane == 0) {
            if (is64) { src = (int)ei64[e]; dst = (int)ei64[E + e]; }
            else      { src = ei32[e];      dst = ei32[E + e]; }
            w0 = ew[2 * e];
            w1 = ew[2 * e + 1];
            float th = atan2f(w1, w0);
            int lo = 0, hi = SECT;           // upper_bound
            while (lo < hi) {
                int mid = (lo + hi) >> 1;
                if (sb[mid] <= th) lo = mid + 1; else hi = mid;
            }
            sct = (lo == 0) ? (SECT - 1) : (lo - 1);
        }
        src = __shfl_sync(0xffffffffu, src, 0);
        dst = __shfl_sync(0xffffffffu, dst, 0);
        sct = __shfl_sync(0xffffffffu, sct, 0);
        w0  = __shfl_sync(0xffffffffu, w0, 0);
        w1  = __shfl_sync(0xffffffffu, w1, 0);

        float4 xj = __ldg(reinterpret_cast<const float4*>(x + (size_t)src * D) + lane);
        float4 u4 = __ldg(reinterpret_cast<const float4*>(g_U + sct * D) + lane);
        float4 v4 = __ldg(reinterpret_cast<const float4*>(g_V + sct * D) + lane);

        float4 m;  // (pe + 1) * x_j
        m.x = xj.x * fmaf(w0, u4.x, fmaf(w1, v4.x, 1.f));
        m.y = xj.y * fmaf(w0, u4.y, fmaf(w1, v4.y, 1.f));
        m.z = xj.z * fmaf(w0, u4.z, fmaf(w1, v4.z, 1.f));
        m.w = xj.w * fmaf(w0, u4.w, fmaf(w1, v4.w, 1.f));

        float* p = g_acc + (size_t)dst * D + lane * 4;
        asm volatile("red.global.add.v4.f32 [%0], {%1, %2, %3, %4};"
                     :: "l"(p), "f"(m.x), "f"(m.y), "f"(m.z), "f"(m.w) : "memory");
        if (lane == 0) atomicAdd(&g_cnt[dst], 1.f);
    }
}

// ---------------- K4: [N,256] @ [256,128] + bias, fused BN stats ---------------
// 64 rows x 128 cols per block, BK=16, 8x4 per thread (256 threads).
__global__ __launch_bounds__(256) void k_gemm(const float* __restrict__ x,
                                              const float* __restrict__ W,
                                              const float* __restrict__ bias,
                                              float* __restrict__ out, int N) {
    __shared__ float As[16][64];
    __shared__ float Ws[16][128];
    __shared__ float inv_s[64];
    __shared__ float scol[128], scolq[128];

    int tid = threadIdx.x;
    int row0 = blockIdx.x * 64;
    if (tid < 64) {
        int r = row0 + tid;
        inv_s[tid] = (r < N) ? (1.f / fmaxf(g_cnt[r], 1.f)) : 0.f;
    }
    if (tid < 128) { scol[tid] = 0.f; scolq[tid] = 0.f; }

    int rg = tid >> 5;        // warp id = row group (0..7)
    int cg = tid & 31;        // col group (0..31) -> cols cg*4..cg*4+3
    int lrow = tid >> 2;      // loader row 0..63
    int jg = tid & 3;         // loader j-group

    float acc[8][4];
    #pragma unroll
    for (int i = 0; i < 8; i++)
        #pragma unroll
        for (int c = 0; c < 4; c++) acc[i][c] = 0.f;

    int grow = row0 + lrow;
    __syncthreads();          // inv_s / scol ready

    for (int kt = 0; kt < 16; kt++) {
        // stage A tile (x half then agg/mean half) into registers
        float4 av = make_float4(0.f, 0.f, 0.f, 0.f);
        if (grow < N) {
            if (kt < 8) {
                av = *reinterpret_cast<const float4*>(x + (size_t)grow * D + kt * 16 + jg * 4);
            } else {
                av = *reinterpret_cast<const float4*>(g_acc + (size_t)grow * D + (kt - 8) * 16 + jg * 4);
                float iv = inv_s[lrow];
                av.x *= iv; av.y *= iv; av.z *= iv; av.w *= iv;
            }
        }
        // stage W chunk (rows kt*16..+15, all 128 cols): 2 float4 per thread
        int f1 = tid + 256;
        float4 wv0 = *reinterpret_cast<const float4*>(W + (size_t)(kt * 16 + (tid >> 5)) * D + (tid & 31) * 4);
        float4 wv1 = *reinterpret_cast<const float4*>(W + (size_t)(kt * 16 + (f1 >> 5)) * D + (f1 & 31) * 4);

        __syncthreads();      // previous iteration consumed
        As[jg * 4 + 0][lrow] = av.x;
        As[jg * 4 + 1][lrow] = av.y;
        As[jg * 4 + 2][lrow] = av.z;
        As[jg * 4 + 3][lrow] = av.w;
        *reinterpret_cast<float4*>(&Ws[tid >> 5][(tid & 31) * 4]) = wv0;
        *reinterpret_cast<float4*>(&Ws[f1 >> 5][(f1 & 31) * 4]) = wv1;
        __syncthreads();

        #pragma unroll
        for (int kk = 0; kk < 16; kk++) {
            float4 wv = *reinterpret_cast<float4*>(&Ws[kk][cg * 4]);
            float4 a0 = *reinterpret_cast<float4*>(&As[kk][rg * 8]);
            float4 a1 = *reinterpret_cast<float4*>(&As[kk][rg * 8 + 4]);
            float a[8] = {a0.x, a0.y, a0.z, a0.w, a1.x, a1.y, a1.z, a1.w};
            #pragma unroll
            for (int i = 0; i < 8; i++) {
                acc[i][0] = fmaf(a[i], wv.x, acc[i][0]);
                acc[i][1] = fmaf(a[i], wv.y, acc[i][1]);
                acc[i][2] = fmaf(a[i], wv.z, acc[i][2]);
                acc[i][3] = fmaf(a[i], wv.w, acc[i][3]);
            }
        }
    }

    // epilogue: bias, store out_pre, accumulate BN column stats
    float4 bv = __ldg(reinterpret_cast<const float4*>(bias) + cg);
    float ssum[4] = {0.f, 0.f, 0.f, 0.f};
    float sqs[4]  = {0.f, 0.f, 0.f, 0.f};
    #pragma unroll
    for (int i = 0; i < 8; i++) {
        int r = row0 + rg * 8 + i;
        if (r < N) {
            float v0 = acc[i][0] + bv.x;
            float v1 = acc[i][1] + bv.y;
            float v2 = acc[i][2] + bv.z;
            float v3 = acc[i][3] + bv.w;
            *reinterpret_cast<float4*>(out + (size_t)r * D + cg * 4) = make_float4(v0, v1, v2, v3);
            ssum[0] += v0; sqs[0] += v0 * v0;
            ssum[1] += v1; sqs[1] += v1 * v1;
            ssum[2] += v2; sqs[2] += v2 * v2;
            ssum[3] += v3; sqs[3] += v3 * v3;
        }
    }
    __syncthreads();
    #pragma unroll
    for (int c = 0; c < 4; c++) {
        atomicAdd(&scol[cg * 4 + c],  ssum[c]);
        atomicAdd(&scolq[cg * 4 + c], sqs[c]);
    }
    __syncthreads();
    if (tid < D) {
        atomicAdd(&g_colsum[tid], scol[tid]);
        atomicAdd(&g_colsq[tid],  scolq[tid]);
    }
}

// ---------------- K5: BN finalize + relu + residual (in-place on out) ----------
__global__ void k_bn(const float* __restrict__ x, const float* __restrict__ gamma,
                     const float* __restrict__ beta, float* __restrict__ out, int N) {
    __shared__ float ssc[D], ssh[D];
    int t = threadIdx.x;
    if (t < D) {
        float invN = 1.f / (float)N;
        float mean = g_colsum[t] * invN;
        float var  = g_colsq[t] * invN - mean * mean;
        float sc = gamma[t] * rsqrtf(var + 1e-5f);
        ssc[t] = sc;
        ssh[t] = beta[t] - mean * sc;
    }
    __syncthreads();
    int i = blockIdx.x * blockDim.x + t;
    int tot = N * (D / 4);
    if (i < tot) {
        int c = (i & 31) * 4;
        float4 o  = reinterpret_cast<float4*>(out)[i];
        float4 xr = reinterpret_cast<const float4*>(x)[i];
        o.x = fmaxf(fmaf(o.x, ssc[c + 0], ssh[c + 0]), 0.f) + xr.x;
        o.y = fmaxf(fmaf(o.y, ssc[c + 1], ssh[c + 1]), 0.f) + xr.y;
        o.z = fmaxf(fmaf(o.z, ssc[c + 2], ssh[c + 2]), 0.f) + xr.z;
        o.w = fmaxf(fmaf(o.w, ssc[c + 3], ssh[c + 3]), 0.f) + xr.w;
        reinterpret_cast<float4*>(out)[i] = o;
    }
}

// ---------------- launch --------------------------------------------------------
extern "C" void kernel_launch(void* const* d_in, const int* in_sizes, int n_in,
                              void* d_out, int out_size) {
    const float* x     = (const float*)d_in[0];
    const void*  ei    = d_in[1];
    const float* ew    = (const float*)d_in[2];
    const float* pw1   = (const float*)d_in[3];
    const float* pw2   = (const float*)d_in[4];
    const float* sw    = (const float*)d_in[5];
    const float* sb    = (const float*)d_in[6];
    const float* gamma = (const float*)d_in[7];
    const float* beta  = (const float*)d_in[8];
    float* out = (float*)d_out;

    int N = in_sizes[0] / D;
    int E = in_sizes[1] / 2;

    k_detect<<<1, 32>>>((const int*)ei);
    k_zero<<<4096, 256>>>(N);
    k_bounds<<<1, 256>>>(pw1);
    k_sectors<<<SECT, D>>>(pw1, pw2);
    k_edges<<<4096, 256>>>(x, ei, ew, E);
    k_gemm<<<(N + 63) / 64, 256>>>(x, sw, sb, out, N);
    k_bn<<<(N * (D / 4) + 255) / 256, 256>>>(x, gamma, beta, out, N);
}

// round 6
// speedup vs baseline: 1.4083x; 1.4083x over previous
#include <cuda_runtime.h>
#include <math.h>
#include <stdint.h>

#define D 128
#define NMAX 100000
#define SECT 256

#define PI_F      3.14159265358979f
#define HALFPI_F  1.57079632679490f
#define TWOPI_F   6.28318530717959f

// ---------------- scratch (static device globals; no runtime alloc) ------------
__device__ float g_acc[(size_t)NMAX * D];   // 51.2 MB scatter accumulator
__device__ float g_cnt[NMAX];               // per-dst edge counts
__device__ float g_bounds[SECT];            // sorted sector boundary angles
__device__ float g_U[SECT * D];             // sector tables: pe = w0*U[s] + w1*V[s]
__device__ float g_V[SECT * D];
__device__ float g_colsum[D];               // BN stats
__device__ float g_colsq[D];
__device__ int   g_ei64;                    // 1 if edge_index is int64

// ---------------- K-1: detect edge_index dtype ---------------------------------
__global__ void k_detect(const int* __restrict__ w) {
    if (threadIdx.x == 0 && blockIdx.x == 0) {
        int all0 = 1;
        #pragma unroll
        for (int j = 1; j < 64; j += 2) all0 &= (w[j] == 0);
        g_ei64 = all0;
    }
}

// ---------------- K0: zero scratch ---------------------------------------------
__global__ void k_zero(int n) {
    int nd4 = n * (D / 4);
    float4 z = make_float4(0.f, 0.f, 0.f, 0.f);
    int stride = gridDim.x * blockDim.x;
    for (int i = blockIdx.x * blockDim.x + threadIdx.x; i < nd4; i += stride)
        reinterpret_cast<float4*>(g_acc)[i] = z;
    for (int i = blockIdx.x * blockDim.x + threadIdx.x; i < n; i += stride)
        g_cnt[i] = 0.f;
    if (blockIdx.x == 0 && threadIdx.x < D) {
        g_colsum[threadIdx.x] = 0.f;
        g_colsq[threadIdx.x]  = 0.f;
    }
}

// ---------------- K1: sector boundary angles ------------------------------------
__global__ void k_bounds(const float* __restrict__ pw1) {
    __shared__ float raw[SECT];
    int t = threadIdx.x;
    if (t < D) {
        float A = pw1[t];
        float B = pw1[D + t];
        float phi = atan2f(B, A);
        float c0 = phi + HALFPI_F; if (c0 >  PI_F) c0 -= TWOPI_F;
        float c1 = phi - HALFPI_F; if (c1 < -PI_F) c1 += TWOPI_F;
        raw[2 * t]     = c0;
        raw[2 * t + 1] = c1;
    }
    __syncthreads();
    float v = raw[t];
    int rank = 0;
    #pragma unroll 8
    for (int j = 0; j < SECT; j++) {
        float u = raw[j];
        rank += (u < v) || (u == v && j < t);
    }
    g_bounds[rank] = v;
}

// ---------------- K2: sector tables U,V ----------------------------------------
__global__ void k_sectors(const float* __restrict__ pw1, const float* __restrict__ pw2) {
    __shared__ float Am[D], Bm[D];
    __shared__ float thc_s;
    int s = blockIdx.x;
    int k = threadIdx.x;
    if (k == 0) {
        float b0 = g_bounds[s];
        float b1 = (s < SECT - 1) ? g_bounds[s + 1] : (g_bounds[0] + TWOPI_F);
        thc_s = 0.5f * (b0 + b1);
    }
    __syncthreads();
    float c = cosf(thc_s), sn = sinf(thc_s);
    float A = pw1[k], B = pw1[D + k];
    bool m = fmaf(A, c, B * sn) > 0.f;
    Am[k] = m ? A : 0.f;
    Bm[k] = m ? B : 0.f;
    __syncthreads();
    float u = 0.f, v = 0.f;
    #pragma unroll 8
    for (int d = 0; d < D; d++) {
        float w = pw2[d * D + k];
        u = fmaf(Am[d], w, u);
        v = fmaf(Bm[d], w, v);
    }
    g_U[s * D + k] = u;
    g_V[s * D + k] = v;
}

// ---------------- K3: edges — batched metadata + warp-per-edge vector phase -----
__global__ __launch_bounds__(256) void k_edges(const float* __restrict__ x,
                                               const void* __restrict__ ei_raw,
                                               const float* __restrict__ ew, int E) {
    __shared__ float sbound[SECT];
    int t = threadIdx.x;
    sbound[t] = g_bounds[t];
    __syncthreads();
    const long long* ei64 = (const long long*)ei_raw;
    const int*       ei32 = (const int*)ei_raw;
    int is64 = g_ei64;
    int lane = t & 31;
    int wid  = blockIdx.x * 8 + (t >> 5);
    int stride = gridDim.x * 8 * 32;

    for (int e0 = wid * 32; e0 < E; e0 += stride) {
        int e = e0 + lane;
        int src = 0, dst = 0, sct = 0;
        float w0 = 0.f, w1 = 0.f;
        if (e < E) {
            if (is64) { src = (int)ei64[e]; dst = (int)ei64[E + e]; }
            else      { src = ei32[e];      dst = ei32[E + e]; }
            float2 wv = reinterpret_cast<const float2*>(ew)[e];
            w0 = wv.x; w1 = wv.y;
            float th = atan2f(w1, w0);
            int lo = 0, hi = SECT;
            while (lo < hi) {
                int mid = (lo + hi) >> 1;
                if (sbound[mid] <= th) lo = mid + 1; else hi = mid;
            }
            sct = (lo == 0) ? (SECT - 1) : (lo - 1);
            atomicAdd(&g_cnt[dst], 1.f);
        }
        int cnt = E - e0; if (cnt > 32) cnt = 32;
        for (int i = 0; i < cnt; i++) {
            int   s  = __shfl_sync(0xffffffffu, src, i);
            int   dd = __shfl_sync(0xffffffffu, dst, i);
            int   sc = __shfl_sync(0xffffffffu, sct, i);
            float a0 = __shfl_sync(0xffffffffu, w0, i);
            float a1 = __shfl_sync(0xffffffffu, w1, i);

            float4 xj = __ldg(reinterpret_cast<const float4*>(x + (size_t)s * D) + lane);
            float4 u4 = __ldg(reinterpret_cast<const float4*>(g_U + sc * D) + lane);
            float4 v4 = __ldg(reinterpret_cast<const float4*>(g_V + sc * D) + lane);

            float4 m;
            m.x = xj.x * fmaf(a0, u4.x, fmaf(a1, v4.x, 1.f));
            m.y = xj.y * fmaf(a0, u4.y, fmaf(a1, v4.y, 1.f));
            m.z = xj.z * fmaf(a0, u4.z, fmaf(a1, v4.z, 1.f));
            m.w = xj.w * fmaf(a0, u4.w, fmaf(a1, v4.w, 1.f));

            float* p = g_acc + (size_t)dd * D + lane * 4;
            asm volatile("red.global.add.v4.f32 [%0], {%1, %2, %3, %4};"
                         :: "l"(p), "f"(m.x), "f"(m.y), "f"(m.z), "f"(m.w) : "memory");
        }
    }
}

// ---------------- tf32 helpers --------------------------------------------------
__device__ __forceinline__ void split_tf32(float a, float& hi, float& lo) {
    unsigned hb, lb;
    asm("cvt.rna.tf32.f32 %0, %1;" : "=r"(hb) : "f"(a));
    hi = __uint_as_float(hb);
    float r = a - hi;
    asm("cvt.rna.tf32.f32 %0, %1;" : "=r"(lb) : "f"(r));
    lo = __uint_as_float(lb);
}

__device__ __forceinline__ void mma_tf32(float* d, float a0, float a1, float a2, float a3,
                                         float b0, float b1) {
    asm volatile(
        "mma.sync.aligned.m16n8k8.row.col.f32.tf32.tf32.f32 "
        "{%0,%1,%2,%3}, {%4,%5,%6,%7}, {%8,%9}, {%0,%1,%2,%3};\n"
        : "+f"(d[0]), "+f"(d[1]), "+f"(d[2]), "+f"(d[3])
        : "r"(__float_as_uint(a0)), "r"(__float_as_uint(a1)),
          "r"(__float_as_uint(a2)), "r"(__float_as_uint(a3)),
          "r"(__float_as_uint(b0)), "r"(__float_as_uint(b1)));
}

// ---------------- K4: tensor-core GEMM [N,256]@[256,128], 3xTF32 ----------------
// Block: 128 rows x 128 cols, 256 threads = 8 warps (2 M x 4 N), warp tile 64x32.
// Fused: mean-div on agg half, +bias, out_pre store, BN column stats.
#define LDP 20   // smem row pitch (floats): 20*m mod 32 -> disjoint 4-bank windows
__global__ __launch_bounds__(256, 2) void k_gemm(const float* __restrict__ x,
                                                 const float* __restrict__ W,
                                                 const float* __restrict__ bias,
                                                 float* __restrict__ out, int N) {
    __shared__ float AsH[128 * LDP], AsL[128 * LDP];
    __shared__ float WsH[128 * LDP], WsL[128 * LDP];
    __shared__ float inv_s[128];
    __shared__ float scol[128], scolq[128];

    int tid = threadIdx.x;
    int row0 = blockIdx.x * 128;
    if (tid < 128) {
        int r = row0 + tid;
        inv_s[tid] = (r < N) ? (1.f / fmaxf(g_cnt[r], 1.f)) : 0.f;
        scol[tid] = 0.f; scolq[tid] = 0.f;
    }

    int lane  = tid & 31;
    int warp  = tid >> 5;
    int warpM = warp >> 2;        // 0..1 -> 64-row slab
    int warpN = warp & 3;         // 0..3 -> 32-col slab
    int grp   = lane >> 2;        // 0..7
    int th4   = lane & 3;         // 0..3

    float c[4][4][4];
    #pragma unroll
    for (int mi = 0; mi < 4; mi++)
        #pragma unroll
        for (int ni = 0; ni < 4; ni++)
            #pragma unroll
            for (int j = 0; j < 4; j++) c[mi][ni][j] = 0.f;

    __syncthreads();              // inv_s ready (needed by A staging below)

    for (int kt = 0; kt < 16; kt++) {
        // ---- stage: load globals into registers (2 slots each for A and W) ----
        float4 av[2]; float ainv[2]; int am[2];
        float4 wv[2]; int wk[2], wn[2];
        #pragma unroll
        for (int u = 0; u < 2; u++) {
            int s = tid + u * 256;          // 0..511
            int m  = s >> 2, ch = s & 3;    // A: row m, k-chunk ch (4 floats)
            am[u] = m;
            int r = row0 + m;
            av[u] = make_float4(0.f, 0.f, 0.f, 0.f);
            ainv[u] = 1.f;
            if (r < N) {
                if (kt < 8) {
                    av[u] = *reinterpret_cast<const float4*>(x + (size_t)r * D + kt * 16 + ch * 4);
                } else {
                    av[u] = *reinterpret_cast<const float4*>(g_acc + (size_t)r * D + (kt - 8) * 16 + ch * 4);
                    ainv[u] = inv_s[m];
                }
            }
            int kr = s & 15, n4 = s >> 4;   // W: k-row kr (0..15), n-chunk n4 (0..31)
            wk[u] = kr; wn[u] = n4;
            wv[u] = *reinterpret_cast<const float4*>(W + (size_t)(kt * 16 + kr) * D + n4 * 4);
        }

        __syncthreads();          // previous tile consumed
        #pragma unroll
        for (int u = 0; u < 2; u++) {
            float iv = ainv[u];
            float h0, l0, h1, l1, h2, l2, h3, l3;
            split_tf32(av[u].x * iv, h0, l0);
            split_tf32(av[u].y * iv, h1, l1);
            split_tf32(av[u].z * iv, h2, l2);
            split_tf32(av[u].w * iv, h3, l3);
            int s = tid + u * 256;
            int base = am[u] * LDP + (s & 3) * 4;
            *reinterpret_cast<float4*>(&AsH[base]) = make_float4(h0, h1, h2, h3);
            *reinterpret_cast<float4*>(&AsL[base]) = make_float4(l0, l1, l2, l3);
            // W transposed into [n][k]
            float wh, wl;
            split_tf32(wv[u].x, wh, wl); WsH[(wn[u]*4+0)*LDP + wk[u]] = wh; WsL[(wn[u]*4+0)*LDP + wk[u]] = wl;
            split_tf32(wv[u].y, wh, wl); WsH[(wn[u]*4+1)*LDP + wk[u]] = wh; WsL[(wn[u]*4+1)*LDP + wk[u]] = wl;
            split_tf32(wv[u].z, wh, wl); WsH[(wn[u]*4+2)*LDP + wk[u]] = wh; WsL[(wn[u]*4+2)*LDP + wk[u]] = wl;
            split_tf32(wv[u].w, wh, wl); WsH[(wn[u]*4+3)*LDP + wk[u]] = wh; WsL[(wn[u]*4+3)*LDP + wk[u]] = wl;
        }
        __syncthreads();

        // ---- compute: 2 k-steps of 8 ----
        #pragma unroll
        for (int ks = 0; ks < 2; ks++) {
            int k0 = ks * 8;
            float bh[4][2], bl[4][2];
            #pragma unroll
            for (int ni = 0; ni < 4; ni++) {
                int n = (warpN * 32 + ni * 8 + grp) * LDP + k0 + th4;
                bh[ni][0] = WsH[n];     bh[ni][1] = WsH[n + 4];
                bl[ni][0] = WsL[n];     bl[ni][1] = WsL[n + 4];
            }
            #pragma unroll
            for (int mi = 0; mi < 4; mi++) {
                int m = (warpM * 64 + mi * 16 + grp) * LDP + k0 + th4;
                float ah0 = AsH[m],           ah2 = AsH[m + 4];
                float ah1 = AsH[m + 8 * LDP], ah3 = AsH[m + 8 * LDP + 4];
                float al0 = AsL[m],           al2 = AsL[m + 4];
                float al1 = AsL[m + 8 * LDP], al3 = AsL[m + 8 * LDP + 4];
                #pragma unroll
                for (int ni = 0; ni < 4; ni++) {
                    mma_tf32(c[mi][ni], ah0, ah1, ah2, ah3, bh[ni][0], bh[ni][1]);
                    mma_tf32(c[mi][ni], ah0, ah1, ah2, ah3, bl[ni][0], bl[ni][1]);
                    mma_tf32(c[mi][ni], al0, al1, al2, al3, bh[ni][0], bh[ni][1]);
                }
            }
        }
    }

    // ---- epilogue: bias + store + BN stats (warp-reduced, then shared/global) --
    float ss[4][2], qq[4][2];
    #pragma unroll
    for (int ni = 0; ni < 4; ni++) { ss[ni][0]=ss[ni][1]=qq[ni][0]=qq[ni][1]=0.f; }

    #pragma unroll
    for (int ni = 0; ni < 4; ni++) {
        int col = warpN * 32 + ni * 8 + 2 * th4;
        float b0 = __ldg(bias + col), b1 = __ldg(bias + col + 1);
        #pragma unroll
        for (int mi = 0; mi < 4; mi++) {
            int rlo = row0 + warpM * 64 + mi * 16 + grp;
            if (rlo < N) {
                float v0 = c[mi][ni][0] + b0;
                float v1 = c[mi][ni][1] + b1;
                *reinterpret_cast<float2*>(out + (size_t)rlo * D + col) = make_float2(v0, v1);
                ss[ni][0] += v0; qq[ni][0] += v0 * v0;
                ss[ni][1] += v1; qq[ni][1] += v1 * v1;
            }
            int rhi = rlo + 8;
            if (rhi < N) {
                float v2 = c[mi][ni][2] + b0;
                float v3 = c[mi][ni][3] + b1;
                *reinterpret_cast<float2*>(out + (size_t)rhi * D + col) = make_float2(v2, v3);
                ss[ni][0] += v2; qq[ni][0] += v2 * v2;
                ss[ni][1] += v3; qq[ni][1] += v3 * v3;
            }
        }
    }
    // reduce across the 8 lanes sharing each column (stride-4 lane groups)
    #pragma unroll
    for (int ni = 0; ni < 4; ni++)
        #pragma unroll
        for (int j = 0; j < 2; j++) {
            float s = ss[ni][j], q = qq[ni][j];
            #pragma unroll
            for (int off = 4; off < 32; off <<= 1) {
                s += __shfl_xor_sync(0xffffffffu, s, off);
                q += __shfl_xor_sync(0xffffffffu, q, off);
            }
            if (lane < 4) {
                int col = warpN * 32 + ni * 8 + 2 * lane + j;
                atomicAdd(&scol[col],  s);
                atomicAdd(&scolq[col], q);
            }
        }
    __syncthreads();
    if (tid < D) {
        atomicAdd(&g_colsum[tid], scol[tid]);
        atomicAdd(&g_colsq[tid],  scolq[tid]);
    }
}

// ---------------- K5: BN finalize + relu + residual -----------------------------
__global__ void k_bn(const float* __restrict__ x, const float* __restrict__ gamma,
                     const float* __restrict__ beta, float* __restrict__ out, int N) {
    __shared__ float ssc[D], ssh[D];
    int t = threadIdx.x;
    if (t < D) {
        float invN = 1.f / (float)N;
        float mean = g_colsum[t] * invN;
        float var  = g_colsq[t] * invN - mean * mean;
        float sc = gamma[t] * rsqrtf(var + 1e-5f);
        ssc[t] = sc;
        ssh[t] = beta[t] - mean * sc;
    }
    __syncthreads();
    int i = blockIdx.x * blockDim.x + t;
    int tot = N * (D / 4);
    if (i < tot) {
        int c = (i & 31) * 4;
        float4 o  = reinterpret_cast<float4*>(out)[i];
        float4 xr = reinterpret_cast<const float4*>(x)[i];
        o.x = fmaxf(fmaf(o.x, ssc[c + 0], ssh[c + 0]), 0.f) + xr.x;
        o.y = fmaxf(fmaf(o.y, ssc[c + 1], ssh[c + 1]), 0.f) + xr.y;
        o.z = fmaxf(fmaf(o.z, ssc[c + 2], ssh[c + 2]), 0.f) + xr.z;
        o.w = fmaxf(fmaf(o.w, ssc[c + 3], ssh[c + 3]), 0.f) + xr.w;
        reinterpret_cast<float4*>(out)[i] = o;
    }
}

// ---------------- launch --------------------------------------------------------
extern "C" void kernel_launch(void* const* d_in, const int* in_sizes, int n_in,
                              void* d_out, int out_size) {
    const float* x     = (const float*)d_in[0];
    const void*  ei    = d_in[1];
    const float* ew    = (const float*)d_in[2];
    const float* pw1   = (const float*)d_in[3];
    const float* pw2   = (const float*)d_in[4];
    const float* sw    = (const float*)d_in[5];
    const float* sb    = (const float*)d_in[6];
    const float* gamma = (const float*)d_in[7];
    const float* beta  = (const float*)d_in[8];
    float* out = (float*)d_out;

    int N = in_sizes[0] / D;
    int E = in_sizes[1] / 2;

    k_detect<<<1, 32>>>((const int*)ei);
    k_zero<<<4096, 256>>>(N);
    k_bounds<<<1, 256>>>(pw1);
    k_sectors<<<SECT, D>>>(pw1, pw2);
    k_edges<<<4096, 256>>>(x, ei, ew, E);
    k_gemm<<<(N + 127) / 128, 256>>>(x, sw, sb, out, N);
    k_bn<<<(N * (D / 4) + 255) / 256, 256>>>(x, gamma, beta, out, N);
}